// round 1
// baseline (speedup 1.0000x reference)
#include <cuda_runtime.h>
#include <cuda_bf16.h>

// Problem constants
#define STEPS 128
#define BATCH 256
#define D1 1024
#define D2 1024
#define M_ROWS (127 * BATCH)      // 32512 rows of lin
#define PLANE (BATCH * D2)        // 262144 elements per timestep
#define PLANE4 (PLANE / 4)        // 65536 float4s per timestep
#define TOTAL4 (STEPS * PLANE4)   // float4s per output tensor

// 133 MB scratch for lin = input[:-1] @ W^T, shape [127*256, 1024]
__device__ float g_lin[(size_t)M_ROWS * D2];

// ---------------------------------------------------------------------------
// Kernel 1: fp32 SIMT GEMM  C[m][n] = sum_k A[m][k] * W[n][k]
// A: [M_ROWS, 1024] row-major (input steps 0..126), W: [1024, 1024] row-major.
// 128x128 block tile, 16-wide K tile, 256 threads, 8x8 per-thread microtile.
// ---------------------------------------------------------------------------
#define TM 128
#define TN 128
#define TKK 16

__global__ __launch_bounds__(256, 1)
void gemm_fp32_kernel(const float* __restrict__ A, const float* __restrict__ W) {
    __shared__ float As[TKK][TM + 4];
    __shared__ float Bs[TKK][TN + 4];

    const int m0 = blockIdx.y * TM;
    const int n0 = blockIdx.x * TN;
    const int t  = threadIdx.x;
    const int tx = t & 15;         // 0..15 -> 8 cols each
    const int ty = t >> 4;         // 0..15 -> 8 rows each

    float acc[8][8];
#pragma unroll
    for (int i = 0; i < 8; i++)
#pragma unroll
        for (int j = 0; j < 8; j++) acc[i][j] = 0.0f;

    for (int k0 = 0; k0 < D1; k0 += TKK) {
        // Load 128x16 tiles of A and W (512 float4 each; 2 per thread each)
#pragma unroll
        for (int i = 0; i < 2; i++) {
            int lid = t + i * 256;
            int row = lid >> 2;            // 0..127
            int c4  = (lid & 3) << 2;      // 0,4,8,12
            float4 va = *(const float4*)&A[(size_t)(m0 + row) * D1 + k0 + c4];
            As[c4 + 0][row] = va.x;
            As[c4 + 1][row] = va.y;
            As[c4 + 2][row] = va.z;
            As[c4 + 3][row] = va.w;
            float4 vb = *(const float4*)&W[(size_t)(n0 + row) * D1 + k0 + c4];
            Bs[c4 + 0][row] = vb.x;
            Bs[c4 + 1][row] = vb.y;
            Bs[c4 + 2][row] = vb.z;
            Bs[c4 + 3][row] = vb.w;
        }
        __syncthreads();

#pragma unroll
        for (int kk = 0; kk < TKK; kk++) {
            float a[8], b[8];
#pragma unroll
            for (int i = 0; i < 8; i++) a[i] = As[kk][ty * 8 + i];
#pragma unroll
            for (int j = 0; j < 8; j++) b[j] = Bs[kk][tx * 8 + j];
#pragma unroll
            for (int i = 0; i < 8; i++)
#pragma unroll
                for (int j = 0; j < 8; j++)
                    acc[i][j] = fmaf(a[i], b[j], acc[i][j]);
        }
        __syncthreads();
    }

    // Store to g_lin
#pragma unroll
    for (int i = 0; i < 8; i++) {
        int m = m0 + ty * 8 + i;
#pragma unroll
        for (int j = 0; j < 8; j += 4) {
            float4 v = make_float4(acc[i][j], acc[i][j + 1], acc[i][j + 2], acc[i][j + 3]);
            *(float4*)&g_lin[(size_t)m * D2 + n0 + tx * 8 + j] = v;
        }
    }
}

// ---------------------------------------------------------------------------
// Kernel 2: sequential LIF scan over 127 steps. One thread per float4 of the
// (batch, d2) plane. Coalesced; next lin load is prefetched.
// out layout: [spk(128,256,1024) | V | I], fp32.
// ---------------------------------------------------------------------------
__global__ __launch_bounds__(256, 8)
void scan_kernel(float* __restrict__ out) {
    const float ALPHA = 0.7788007830714049f;  // exp(-1/4)
    const float BETA  = 0.9512294245007140f;  // exp(-1/20)

    int j = blockIdx.x * blockDim.x + threadIdx.x;  // 0..PLANE4-1
    if (j >= PLANE4) return;

    const float4* lin = (const float4*)g_lin;
    float4* spk = (float4*)out;
    float4* V   = spk + TOTAL4;
    float4* I   = V + TOTAL4;

    float sx = 0.f, sy = 0.f, sz = 0.f, sw = 0.f;  // syn
    float mx = 0.f, my = 0.f, mz = 0.f, mw = 0.f;  // mem

    // t = 0: all zeros (out buffer is poisoned; must write)
    float4 z = make_float4(0.f, 0.f, 0.f, 0.f);
    spk[j] = z; V[j] = z; I[j] = z;

    float4 cur = lin[j];  // lin step 0 (used at t=1)

#pragma unroll 1
    for (int t = 1; t < STEPS; t++) {
        float4 nxt = cur;
        if (t < STEPS - 1) nxt = lin[(size_t)t * PLANE4 + j];

        // reset from PREVIOUS mem, then decay+integrate, then spike
        float kx = (mx > 1.0f) ? 0.0f : 1.0f;
        float ky = (my > 1.0f) ? 0.0f : 1.0f;
        float kz = (mz > 1.0f) ? 0.0f : 1.0f;
        float kw = (mw > 1.0f) ? 0.0f : 1.0f;

        sx = ALPHA * sx + cur.x;
        sy = ALPHA * sy + cur.y;
        sz = ALPHA * sz + cur.z;
        sw = ALPHA * sw + cur.w;

        mx = (BETA * mx + sx) * kx;
        my = (BETA * my + sy) * ky;
        mz = (BETA * mz + sz) * kz;
        mw = (BETA * mw + sw) * kw;

        float4 o;
        o.x = (mx > 1.0f) ? 1.0f : 0.0f;
        o.y = (my > 1.0f) ? 1.0f : 0.0f;
        o.z = (mz > 1.0f) ? 1.0f : 0.0f;
        o.w = (mw > 1.0f) ? 1.0f : 0.0f;

        size_t off = (size_t)t * PLANE4 + j;
        spk[off] = o;
        V[off]   = make_float4(mx, my, mz, mw);
        I[off]   = make_float4(sx, sy, sz, sw);

        cur = nxt;
    }
}

extern "C" void kernel_launch(void* const* d_in, const int* in_sizes, int n_in,
                              void* d_out, int out_size) {
    const float* input  = (const float*)d_in[0];   // [128, 256, 1024]
    const float* weight = (const float*)d_in[1];   // [1024, 1024]
    float* out = (float*)d_out;                    // [3, 128, 256, 1024]

    dim3 ggrid(D2 / TN, M_ROWS / TM);              // (8, 254)
    gemm_fp32_kernel<<<ggrid, 256>>>(input, weight);

    scan_kernel<<<PLANE4 / 256, 256>>>(out);
}

// round 5
// speedup vs baseline: 1.1043x; 1.1043x over previous
#include <cuda_runtime.h>
#include <cuda_bf16.h>
#include <cstdint>

// ---------------------------------------------------------------------------
// Problem constants
// ---------------------------------------------------------------------------
#define STEPS 128
#define BATCH 256
#define D1 1024
#define D2 1024
#define M_ROWS (127 * BATCH)        // 32512
#define PLANE (BATCH * D2)          // 262144
#define PLANE2 (PLANE / 2)
#define TOTAL2 (STEPS * PLANE2)

// GEMM tiling: CTA 128(M) x 64(N), K-chunk 32, 3-limb A and W tiles per stage.
#define KST 32
#define ROWH 40                     // bf16 per smem row (32 + 8 pad)
#define TA_H (128 * ROWH)           // 5120 halfs per A limb tile
#define TB_H (64 * ROWH)            // 2560 halfs per W limb tile
#define BOFF_H (3 * TA_H)           // 15360
#define STAGE_H (3 * TA_H + 3 * TB_H)   // 23040 halfs
#define STAGE_B (STAGE_H * 2)       // 46080 bytes
#define NSTAGES 3
#define SMEM_BYTES (NSTAGES * STAGE_B)  // 138240
#define NKC 32                      // 1024 / 32 k-chunks

// ---------------------------------------------------------------------------
// Device scratch
// ---------------------------------------------------------------------------
__device__ float         g_lin[(size_t)M_ROWS * D2];     // 133 MB
__device__ __nv_bfloat16 g_A[3][(size_t)M_ROWS * D1];    // 3 x 66.6 MB
__device__ __nv_bfloat16 g_W[3][(size_t)D2 * D1];        // 3 x 2 MB

// ---------------------------------------------------------------------------
// Exact-ish 3-limb bf16 split: x ~= h0 + h1 + h2 (error <= 2^-25 |x|)
// ---------------------------------------------------------------------------
__global__ __launch_bounds__(256) void split3(const float* __restrict__ src,
                                              __nv_bfloat16* __restrict__ o0,
                                              __nv_bfloat16* __restrict__ o1,
                                              __nv_bfloat16* __restrict__ o2, int n8) {
    int i = blockIdx.x * blockDim.x + threadIdx.x;
    if (i >= n8) return;
    const float4* s = (const float4*)(src + (size_t)i * 8);
    float4 v0 = s[0], v1 = s[1];
    float x[8] = {v0.x, v0.y, v0.z, v0.w, v1.x, v1.y, v1.z, v1.w};
    unsigned short h0[8], h1[8], h2[8];
#pragma unroll
    for (int q = 0; q < 8; q++) {
        __nv_bfloat16 a = __float2bfloat16_rn(x[q]);
        float r1 = x[q] - __bfloat162float(a);
        __nv_bfloat16 b = __float2bfloat16_rn(r1);
        float r2 = r1 - __bfloat162float(b);
        __nv_bfloat16 c = __float2bfloat16_rn(r2);
        h0[q] = __bfloat16_as_ushort(a);
        h1[q] = __bfloat16_as_ushort(b);
        h2[q] = __bfloat16_as_ushort(c);
    }
    uint4 p;
    p.x = h0[0] | ((uint32_t)h0[1] << 16); p.y = h0[2] | ((uint32_t)h0[3] << 16);
    p.z = h0[4] | ((uint32_t)h0[5] << 16); p.w = h0[6] | ((uint32_t)h0[7] << 16);
    ((uint4*)o0)[i] = p;
    p.x = h1[0] | ((uint32_t)h1[1] << 16); p.y = h1[2] | ((uint32_t)h1[3] << 16);
    p.z = h1[4] | ((uint32_t)h1[5] << 16); p.w = h1[6] | ((uint32_t)h1[7] << 16);
    ((uint4*)o1)[i] = p;
    p.x = h2[0] | ((uint32_t)h2[1] << 16); p.y = h2[2] | ((uint32_t)h2[3] << 16);
    p.z = h2[4] | ((uint32_t)h2[5] << 16); p.w = h2[6] | ((uint32_t)h2[7] << 16);
    ((uint4*)o2)[i] = p;
}

// ---------------------------------------------------------------------------
// MMA / ldmatrix helpers
// ---------------------------------------------------------------------------
__device__ __forceinline__ void ldm4(uint32_t* r, uint32_t a) {
    asm volatile("ldmatrix.sync.aligned.m8n8.x4.shared.b16 {%0,%1,%2,%3}, [%4];"
        : "=r"(r[0]), "=r"(r[1]), "=r"(r[2]), "=r"(r[3]) : "r"(a));
}
// chained: c += a*b
__device__ __forceinline__ void mma_acc(float* c, const uint32_t* a, const uint32_t* b) {
    asm volatile(
        "mma.sync.aligned.m16n8k16.row.col.f32.bf16.bf16.f32 "
        "{%0,%1,%2,%3}, {%4,%5,%6,%7}, {%8,%9}, {%0,%1,%2,%3};"
        : "+f"(c[0]), "+f"(c[1]), "+f"(c[2]), "+f"(c[3])
        : "r"(a[0]), "r"(a[1]), "r"(a[2]), "r"(a[3]), "r"(b[0]), "r"(b[1]));
}
// fresh chain: d = a*b + 0   (separate d/c operands; no register reset needed)
__device__ __forceinline__ void mma_zro(float* d, const uint32_t* a, const uint32_t* b) {
    asm volatile(
        "mma.sync.aligned.m16n8k16.row.col.f32.bf16.bf16.f32 "
        "{%0,%1,%2,%3}, {%4,%5,%6,%7}, {%8,%9}, {%10,%10,%10,%10};"
        : "=f"(d[0]), "=f"(d[1]), "=f"(d[2]), "=f"(d[3])
        : "r"(a[0]), "r"(a[1]), "r"(a[2]), "r"(a[3]), "r"(b[0]), "r"(b[1]),
          "f"(0.0f));
}

// ---------------------------------------------------------------------------
// GEMM: lin = A @ W^T via 6 bf16 limb products.
// Product 00 (scale 1): per-k-chunk 2-HMMA chain -> RN FADD into c_total
// (kills tensor-core RZ truncation bias). Products 01,10,02,11,20: chained in
// acc_lo (magnitude ~2^-8, RZ bias negligible), added once at the end.
// CTA 128x64, 256 threads (8 warps: 4M x 2N of 32x32), 3-stage cp.async.
// ---------------------------------------------------------------------------
__global__ __launch_bounds__(256, 1) void gemm_limb_kernel() {
    extern __shared__ __nv_bfloat16 smp[];
    const int tid = threadIdx.x, lane = tid & 31, wid = tid >> 5;
    const int wm = wid & 3, wn = wid >> 2;
    const int r4 = lane >> 2, cq = lane & 3;
    const int nb = blockIdx.x, mb = blockIdx.y;
    const int m0 = mb * 128, n0 = nb * 64;
    uint32_t smem_base = (uint32_t)__cvta_generic_to_shared(smp);

    float ct[2][4][4], ah[2][4][4], al[2][4][4];
#pragma unroll
    for (int im = 0; im < 2; im++)
#pragma unroll
        for (int jn = 0; jn < 4; jn++)
#pragma unroll
            for (int q = 0; q < 4; q++) { ct[im][jn][q] = 0.f; al[im][jn][q] = 0.f; }

    const __nv_bfloat16* Ab = &g_A[0][0] + (size_t)m0 * D1;
    const __nv_bfloat16* Wb = &g_W[0][0] + (size_t)n0 * D1;
    const size_t APL = (size_t)M_ROWS * D1;
    const size_t WPL = (size_t)D2 * D1;

    auto fill = [&](int buf, int kc) {
        int k0 = kc * KST;
        uint32_t sb = smem_base + (uint32_t)buf * STAGE_B;
#pragma unroll
        for (int i = 0; i < 6; i++) {            // A: 3 tiles x 128 rows x 4 x 16B
            int ch = i * 256 + tid;
            int tile = ch >> 9;
            int r = (ch >> 2) & 127;
            int q = ch & 3;
            const void* src = Ab + (size_t)tile * APL + (size_t)r * D1 + k0 + q * 8;
            uint32_t dst = sb + (uint32_t)(tile * TA_H + r * ROWH + q * 8) * 2;
            asm volatile("cp.async.cg.shared.global [%0], [%1], 16;" :: "r"(dst), "l"(src));
        }
#pragma unroll
        for (int i = 0; i < 3; i++) {            // W: 3 tiles x 64 rows x 4 x 16B
            int ch = i * 256 + tid;
            int tile = ch >> 8;
            int r = (ch >> 2) & 63;
            int q = ch & 3;
            const void* src = Wb + (size_t)tile * WPL + (size_t)r * D1 + k0 + q * 8;
            uint32_t dst = sb + (uint32_t)(BOFF_H + tile * TB_H + r * ROWH + q * 8) * 2;
            asm volatile("cp.async.cg.shared.global [%0], [%1], 16;" :: "r"(dst), "l"(src));
        }
        asm volatile("cp.async.commit_group;");
    };

    fill(0, 0);
    fill(1, 1);

    // ldmatrix per-lane address components (in halfs)
    const int aRow = wm * 32 + (lane & 15);
    const int aK   = (lane >> 4) * 8;
    const int bRow = wn * 32 + (lane >> 4) * 8 + (lane & 7);
    const int bK   = ((lane >> 3) & 1) * 8;

    const int pla[5] = {0, 1, 0, 1, 2};     // small products (a-limb)
    const int plb[5] = {1, 0, 2, 1, 0};     // small products (b-limb)

    for (int s = 0; s < NKC; s++) {
        if (s + 2 < NKC) { fill((s + 2) % 3, s + 2); asm volatile("cp.async.wait_group 2;"); }
        else if (s + 1 < NKC) asm volatile("cp.async.wait_group 1;");
        else asm volatile("cp.async.wait_group 0;");
        __syncthreads();

        uint32_t sb = smem_base + (uint32_t)(s % 3) * STAGE_B;
#pragma unroll
        for (int ksub = 0; ksub < 2; ksub++) {
            uint32_t a[3][2][4];
            uint32_t b[3][4][2];
#pragma unroll
            for (int la = 0; la < 3; la++) {
#pragma unroll
                for (int im = 0; im < 2; im++) {
                    uint32_t ad = sb + (uint32_t)(la * TA_H + (aRow + im * 16) * ROWH
                                                  + ksub * 16 + aK) * 2;
                    ldm4(a[la][im], ad);
                }
#pragma unroll
                for (int jp = 0; jp < 2; jp++) {
                    uint32_t bd = sb + (uint32_t)(BOFF_H + la * TB_H + (bRow + jp * 16) * ROWH
                                                  + ksub * 16 + bK) * 2;
                    uint32_t t[4];
                    ldm4(t, bd);
                    b[la][jp * 2][0] = t[0]; b[la][jp * 2][1] = t[1];
                    b[la][jp * 2 + 1][0] = t[2]; b[la][jp * 2 + 1][1] = t[3];
                }
            }
            // hi product 00: fresh 2-HMMA chain per k-chunk
#pragma unroll
            for (int im = 0; im < 2; im++)
#pragma unroll
                for (int jn = 0; jn < 4; jn++) {
                    if (ksub == 0) mma_zro(ah[im][jn], a[0][im], b[0][jn]);
                    else           mma_acc(ah[im][jn], a[0][im], b[0][jn]);
                }
            // small products: long chain at small magnitude (RZ bias harmless)
#pragma unroll
            for (int p = 0; p < 5; p++)
#pragma unroll
                for (int im = 0; im < 2; im++)
#pragma unroll
                    for (int jn = 0; jn < 4; jn++)
                        mma_acc(al[im][jn], a[pla[p]][im], b[plb[p]][jn]);
        }
        // RN dump of hi chunk-partial into total (CUDA-core FADD)
#pragma unroll
        for (int im = 0; im < 2; im++)
#pragma unroll
            for (int jn = 0; jn < 4; jn++)
#pragma unroll
                for (int q = 0; q < 4; q++)
                    ct[im][jn][q] += ah[im][jn][q];
        __syncthreads();
    }

    // add small-product accumulator, store
#pragma unroll
    for (int im = 0; im < 2; im++) {
#pragma unroll
        for (int jn = 0; jn < 4; jn++) {
#pragma unroll
            for (int q = 0; q < 4; q++) ct[im][jn][q] += al[im][jn][q];
            int row = m0 + wm * 32 + im * 16 + r4;
            int col = n0 + wn * 32 + jn * 8 + cq * 2;
            *(float2*)&g_lin[(size_t)row * D2 + col] =
                make_float2(ct[im][jn][0], ct[im][jn][1]);
            *(float2*)&g_lin[(size_t)(row + 8) * D2 + col] =
                make_float2(ct[im][jn][2], ct[im][jn][3]);
        }
    }
}

// ---------------------------------------------------------------------------
// LIF scan: one thread per float2 of the (batch, d2) plane.
// ---------------------------------------------------------------------------
__global__ __launch_bounds__(256, 8) void scan_kernel(float* __restrict__ out) {
    const float ALPHA = 0.7788007830714049f;  // exp(-1/4)
    const float BETA  = 0.9512294245007140f;  // exp(-1/20)

    int j = blockIdx.x * blockDim.x + threadIdx.x;

    const float2* lin = (const float2*)g_lin;
    float2* spk = (float2*)out;
    float2* V   = spk + TOTAL2;
    float2* I   = V + TOTAL2;

    float sx = 0.f, sy = 0.f, mx = 0.f, my = 0.f;

    float2 z = make_float2(0.f, 0.f);
    spk[j] = z; V[j] = z; I[j] = z;

    float2 cur = lin[j];

#pragma unroll 1
    for (int t = 1; t < STEPS; t++) {
        float2 nxt = cur;
        if (t < STEPS - 1) nxt = lin[(size_t)t * PLANE2 + j];

        float kx = (mx > 1.0f) ? 0.0f : 1.0f;
        float ky = (my > 1.0f) ? 0.0f : 1.0f;

        sx = ALPHA * sx + cur.x;
        sy = ALPHA * sy + cur.y;
        mx = (BETA * mx + sx) * kx;
        my = (BETA * my + sy) * ky;

        float2 o;
        o.x = (mx > 1.0f) ? 1.0f : 0.0f;
        o.y = (my > 1.0f) ? 1.0f : 0.0f;

        size_t off = (size_t)t * PLANE2 + j;
        spk[off] = o;
        V[off]   = make_float2(mx, my);
        I[off]   = make_float2(sx, sy);

        cur = nxt;
    }
}

// ---------------------------------------------------------------------------
extern "C" void kernel_launch(void* const* d_in, const int* in_sizes, int n_in,
                              void* d_out, int out_size) {
    const float* input  = (const float*)d_in[0];   // [128, 256, 1024]
    const float* weight = (const float*)d_in[1];   // [1024, 1024]
    float* out = (float*)d_out;                    // [3, 128, 256, 1024]

    __nv_bfloat16 *pA, *pW;
    cudaGetSymbolAddress((void**)&pA, g_A);
    cudaGetSymbolAddress((void**)&pW, g_W);
    const size_t APL = (size_t)M_ROWS * D1;
    const size_t WPL = (size_t)D2 * D1;

    int nA8 = (M_ROWS * D1) / 8;
    int nW8 = (D2 * D1) / 8;
    split3<<<(nA8 + 255) / 256, 256>>>(input, pA, pA + APL, pA + 2 * APL, nA8);
    split3<<<(nW8 + 255) / 256, 256>>>(weight, pW, pW + WPL, pW + 2 * WPL, nW8);

    cudaFuncSetAttribute(gemm_limb_kernel, cudaFuncAttributeMaxDynamicSharedMemorySize, SMEM_BYTES);
    gemm_limb_kernel<<<dim3(D2 / 64, M_ROWS / 128), 256, SMEM_BYTES>>>();

    scan_kernel<<<PLANE2 / 256, 256>>>(out);
}

// round 6
// speedup vs baseline: 1.3199x; 1.1953x over previous
#include <cuda_runtime.h>
#include <cuda_bf16.h>
#include <cstdint>

// ---------------------------------------------------------------------------
// Problem constants
// ---------------------------------------------------------------------------
#define STEPS 128
#define BATCH 256
#define D1 1024
#define D2 1024
#define M_ROWS (127 * BATCH)        // 32512
#define PLANE (BATCH * D2)          // 262144
#define TOTAL (STEPS * PLANE)

// GEMM tiling: CTA 128(M) x 128(N), K-chunk 64, 512 threads (16 warps 4x4).
#define KC 64
#define NCH 16                      // 1024 / 64 chunks
#define ROWH 72                     // 64 data halfs + 8 pad (144B row, conflict-free)
#define TILE_H (128 * ROWH)         // 9216 halfs per limb tile
#define STAGE_H (6 * TILE_H)        // A0,A1,A2,W0,W1,W2
#define STAGE_B (STAGE_H * 2)       // 110592 bytes
#define SMEM_BYTES (2 * STAGE_B)    // 221184 bytes

// ---------------------------------------------------------------------------
// Device scratch
// ---------------------------------------------------------------------------
__device__ float         g_lin[(size_t)M_ROWS * D2];     // 133 MB
__device__ __nv_bfloat16 g_A[3][(size_t)M_ROWS * D1];    // 3 x 66.6 MB
__device__ __nv_bfloat16 g_W[3][(size_t)D2 * D1];        // 3 x 2 MB

// ---------------------------------------------------------------------------
// 3-limb bf16 split: x ~= h0 + h1 + h2 (error <= 2^-25 |x|)
// ---------------------------------------------------------------------------
__global__ __launch_bounds__(256) void split3(const float* __restrict__ src,
                                              __nv_bfloat16* __restrict__ o0,
                                              __nv_bfloat16* __restrict__ o1,
                                              __nv_bfloat16* __restrict__ o2, int n8) {
    int i = blockIdx.x * blockDim.x + threadIdx.x;
    if (i >= n8) return;
    const float4* s = (const float4*)(src + (size_t)i * 8);
    float4 v0 = s[0], v1 = s[1];
    float x[8] = {v0.x, v0.y, v0.z, v0.w, v1.x, v1.y, v1.z, v1.w};
    unsigned short h0[8], h1[8], h2[8];
#pragma unroll
    for (int q = 0; q < 8; q++) {
        __nv_bfloat16 a = __float2bfloat16_rn(x[q]);
        float r1 = x[q] - __bfloat162float(a);
        __nv_bfloat16 b = __float2bfloat16_rn(r1);
        float r2 = r1 - __bfloat162float(b);
        __nv_bfloat16 c = __float2bfloat16_rn(r2);
        h0[q] = __bfloat16_as_ushort(a);
        h1[q] = __bfloat16_as_ushort(b);
        h2[q] = __bfloat16_as_ushort(c);
    }
    uint4 p;
    p.x = h0[0] | ((uint32_t)h0[1] << 16); p.y = h0[2] | ((uint32_t)h0[3] << 16);
    p.z = h0[4] | ((uint32_t)h0[5] << 16); p.w = h0[6] | ((uint32_t)h0[7] << 16);
    ((uint4*)o0)[i] = p;
    p.x = h1[0] | ((uint32_t)h1[1] << 16); p.y = h1[2] | ((uint32_t)h1[3] << 16);
    p.z = h1[4] | ((uint32_t)h1[5] << 16); p.w = h1[6] | ((uint32_t)h1[7] << 16);
    ((uint4*)o1)[i] = p;
    p.x = h2[0] | ((uint32_t)h2[1] << 16); p.y = h2[2] | ((uint32_t)h2[3] << 16);
    p.z = h2[4] | ((uint32_t)h2[5] << 16); p.w = h2[6] | ((uint32_t)h2[7] << 16);
    ((uint4*)o2)[i] = p;
}

// ---------------------------------------------------------------------------
// MMA / ldmatrix helpers
// ---------------------------------------------------------------------------
__device__ __forceinline__ void ldm4(uint32_t* r, uint32_t a) {
    asm volatile("ldmatrix.sync.aligned.m8n8.x4.shared.b16 {%0,%1,%2,%3}, [%4];"
        : "=r"(r[0]), "=r"(r[1]), "=r"(r[2]), "=r"(r[3]) : "r"(a));
}
__device__ __forceinline__ void mma_acc(float* c, const uint32_t* a, const uint32_t* b) {
    asm volatile(
        "mma.sync.aligned.m16n8k16.row.col.f32.bf16.bf16.f32 "
        "{%0,%1,%2,%3}, {%4,%5,%6,%7}, {%8,%9}, {%0,%1,%2,%3};"
        : "+f"(c[0]), "+f"(c[1]), "+f"(c[2]), "+f"(c[3])
        : "r"(a[0]), "r"(a[1]), "r"(a[2]), "r"(a[3]), "r"(b[0]), "r"(b[1]));
}
__device__ __forceinline__ void mma_zro(float* d, const uint32_t* a, const uint32_t* b) {
    asm volatile(
        "mma.sync.aligned.m16n8k16.row.col.f32.bf16.bf16.f32 "
        "{%0,%1,%2,%3}, {%4,%5,%6,%7}, {%8,%9}, {%10,%10,%10,%10};"
        : "=f"(d[0]), "=f"(d[1]), "=f"(d[2]), "=f"(d[3])
        : "r"(a[0]), "r"(a[1]), "r"(a[2]), "r"(a[3]), "r"(b[0]), "r"(b[1]),
          "f"(0.0f));
}

// ---------------------------------------------------------------------------
// GEMM: lin = A @ W^T via 6 bf16 limb products.
// Hi product (a0*b0): chain length 1 (fresh d), RN FADD into ct per k16 -> no
// tensor-core RZ bias. Small products (01,10,02,11,20): chained in al at
// ~2^-8 magnitude (RZ bias negligible), added once at the end.
// ---------------------------------------------------------------------------
__global__ __launch_bounds__(512, 1) void gemm_limb_kernel() {
    extern __shared__ __nv_bfloat16 smp[];
    const int tid = threadIdx.x, lane = tid & 31, wid = tid >> 5;
    const int wm = wid & 3, wn = wid >> 2;       // 4(M) x 4(N) warp grid
    const int r4 = lane >> 2, cq = lane & 3;
    const int nb = blockIdx.x, mb = blockIdx.y;
    const int m0 = mb * 128, n0 = nb * 128;
    uint32_t smem_base = (uint32_t)__cvta_generic_to_shared(smp);

    float ct[2][4][4], al[2][4][4];
#pragma unroll
    for (int im = 0; im < 2; im++)
#pragma unroll
        for (int jn = 0; jn < 4; jn++)
#pragma unroll
            for (int q = 0; q < 4; q++) { ct[im][jn][q] = 0.f; al[im][jn][q] = 0.f; }

    const __nv_bfloat16* Ab = &g_A[0][0] + (size_t)m0 * D1;
    const __nv_bfloat16* Wb = &g_W[0][0] + (size_t)n0 * D1;
    const size_t APL = (size_t)M_ROWS * D1;
    const size_t WPL = (size_t)D2 * D1;

    // fill one stage: 6 tiles x 128 rows x 8 x 16B = 6144 chunks / 512 thr = 12
    auto fill = [&](int buf, int kc) {
        int k0 = kc * KC;
        uint32_t sb = smem_base + (uint32_t)buf * STAGE_B;
#pragma unroll
        for (int i = 0; i < 12; i++) {
            int ch = i * 512 + tid;
            int tile = ch >> 10;
            int r = (ch >> 3) & 127;
            int q = ch & 7;
            const void* src = (tile < 3)
                ? (const void*)(Ab + (size_t)tile * APL + (size_t)r * D1 + k0 + q * 8)
                : (const void*)(Wb + (size_t)(tile - 3) * WPL + (size_t)r * D1 + k0 + q * 8);
            uint32_t dst = sb + (uint32_t)(tile * TILE_H + r * ROWH + q * 8) * 2;
            asm volatile("cp.async.cg.shared.global [%0], [%1], 16;" :: "r"(dst), "l"(src));
        }
        asm volatile("cp.async.commit_group;");
    };

    fill(0, 0);
    fill(1, 1);

    // ldmatrix per-lane address components (halfs) — verified mappings (round 5)
    const int aRow = wm * 32 + (lane & 15);
    const int aK   = (lane >> 4) * 8;
    const int bRow = wn * 32 + (lane >> 4) * 8 + (lane & 7);
    const int bK   = ((lane >> 3) & 1) * 8;

    for (int s = 0; s < NCH; s++) {
        asm volatile("cp.async.wait_group 1;");
        __syncthreads();

        uint32_t sb = smem_base + (uint32_t)(s & 1) * STAGE_B;
#pragma unroll
        for (int ksub = 0; ksub < 4; ksub++) {
            // B fragments: 3 limbs x 4 jn
            uint32_t b[3][4][2];
#pragma unroll
            for (int lb = 0; lb < 3; lb++)
#pragma unroll
                for (int jp = 0; jp < 2; jp++) {
                    uint32_t bd = sb + (uint32_t)((3 + lb) * TILE_H
                                   + (bRow + jp * 16) * ROWH + ksub * 16 + bK) * 2;
                    uint32_t t[4];
                    ldm4(t, bd);
                    b[lb][jp * 2][0] = t[0];     b[lb][jp * 2][1] = t[1];
                    b[lb][jp * 2 + 1][0] = t[2]; b[lb][jp * 2 + 1][1] = t[3];
                }
            uint32_t a[2][4];
            // la = 0: hi product (fresh chain + RN dump) and products (0,1),(0,2)
#pragma unroll
            for (int im = 0; im < 2; im++) {
                uint32_t ad = sb + (uint32_t)(0 * TILE_H + (aRow + im * 16) * ROWH
                               + ksub * 16 + aK) * 2;
                ldm4(a[im], ad);
            }
#pragma unroll
            for (int im = 0; im < 2; im++)
#pragma unroll
                for (int jn = 0; jn < 4; jn++) {
                    float t4[4];
                    mma_zro(t4, a[im], b[0][jn]);
#pragma unroll
                    for (int q = 0; q < 4; q++) ct[im][jn][q] += t4[q];
                    mma_acc(al[im][jn], a[im], b[1][jn]);
                    mma_acc(al[im][jn], a[im], b[2][jn]);
                }
            // la = 1: products (1,0),(1,1)
#pragma unroll
            for (int im = 0; im < 2; im++) {
                uint32_t ad = sb + (uint32_t)(1 * TILE_H + (aRow + im * 16) * ROWH
                               + ksub * 16 + aK) * 2;
                ldm4(a[im], ad);
            }
#pragma unroll
            for (int im = 0; im < 2; im++)
#pragma unroll
                for (int jn = 0; jn < 4; jn++) {
                    mma_acc(al[im][jn], a[im], b[0][jn]);
                    mma_acc(al[im][jn], a[im], b[1][jn]);
                }
            // la = 2: product (2,0)
#pragma unroll
            for (int im = 0; im < 2; im++) {
                uint32_t ad = sb + (uint32_t)(2 * TILE_H + (aRow + im * 16) * ROWH
                               + ksub * 16 + aK) * 2;
                ldm4(a[im], ad);
            }
#pragma unroll
            for (int im = 0; im < 2; im++)
#pragma unroll
                for (int jn = 0; jn < 4; jn++)
                    mma_acc(al[im][jn], a[im], b[0][jn]);
        }
        __syncthreads();
        if (s + 2 < NCH) fill(s & 1, s + 2);
    }

    // add small-product accumulator, store
#pragma unroll
    for (int im = 0; im < 2; im++) {
#pragma unroll
        for (int jn = 0; jn < 4; jn++) {
#pragma unroll
            for (int q = 0; q < 4; q++) ct[im][jn][q] += al[im][jn][q];
            int row = m0 + wm * 32 + im * 16 + r4;
            int col = n0 + wn * 32 + jn * 8 + cq * 2;
            *(float2*)&g_lin[(size_t)row * D2 + col] =
                make_float2(ct[im][jn][0], ct[im][jn][1]);
            *(float2*)&g_lin[(size_t)(row + 8) * D2 + col] =
                make_float2(ct[im][jn][2], ct[im][jn][3]);
        }
    }
}

// ---------------------------------------------------------------------------
// LIF scan: one thread per float (262144 threads, 1024 CTAs).
// ---------------------------------------------------------------------------
__global__ __launch_bounds__(256, 8) void scan_kernel(float* __restrict__ out) {
    const float ALPHA = 0.7788007830714049f;  // exp(-1/4)
    const float BETA  = 0.9512294245007140f;  // exp(-1/20)

    int j = blockIdx.x * blockDim.x + threadIdx.x;  // 0..PLANE-1

    const float* lin = g_lin;
    float* spk = out;
    float* V   = spk + TOTAL;
    float* I   = V + TOTAL;

    float sx = 0.f, mx = 0.f;

    spk[j] = 0.f; V[j] = 0.f; I[j] = 0.f;   // t = 0

    float cur = lin[j];

#pragma unroll 1
    for (int t = 1; t < STEPS; t++) {
        float nxt = cur;
        if (t < STEPS - 1) nxt = lin[(size_t)t * PLANE + j];

        float kx = (mx > 1.0f) ? 0.0f : 1.0f;
        sx = ALPHA * sx + cur;
        mx = (BETA * mx + sx) * kx;
        float o = (mx > 1.0f) ? 1.0f : 0.0f;

        size_t off = (size_t)t * PLANE + j;
        spk[off] = o;
        V[off]   = mx;
        I[off]   = sx;

        cur = nxt;
    }
}

// ---------------------------------------------------------------------------
extern "C" void kernel_launch(void* const* d_in, const int* in_sizes, int n_in,
                              void* d_out, int out_size) {
    const float* input  = (const float*)d_in[0];   // [128, 256, 1024]
    const float* weight = (const float*)d_in[1];   // [1024, 1024]
    float* out = (float*)d_out;                    // [3, 128, 256, 1024]

    __nv_bfloat16 *pA, *pW;
    cudaGetSymbolAddress((void**)&pA, g_A);
    cudaGetSymbolAddress((void**)&pW, g_W);
    const size_t APL = (size_t)M_ROWS * D1;
    const size_t WPL = (size_t)D2 * D1;

    int nA8 = (M_ROWS * D1) / 8;
    int nW8 = (D2 * D1) / 8;
    split3<<<(nA8 + 255) / 256, 256>>>(input, pA, pA + APL, pA + 2 * APL, nA8);
    split3<<<(nW8 + 255) / 256, 256>>>(weight, pW, pW + WPL, pW + 2 * WPL, nW8);

    cudaFuncSetAttribute(gemm_limb_kernel, cudaFuncAttributeMaxDynamicSharedMemorySize, SMEM_BYTES);
    gemm_limb_kernel<<<dim3(D2 / 128, M_ROWS / 128), 512, SMEM_BYTES>>>();

    scan_kernel<<<PLANE / 256, 256>>>(out);
}

// round 7
// speedup vs baseline: 2.0999x; 1.5910x over previous
#include <cuda_runtime.h>
#include <cuda_fp16.h>
#include <cstdint>

// ---------------------------------------------------------------------------
// Problem constants
// ---------------------------------------------------------------------------
#define STEPS 128
#define BATCH 256
#define D1 1024
#define D2 1024
#define M_ROWS (127 * BATCH)        // 32512
#define PLANE (BATCH * D2)          // 262144
#define TOTAL (STEPS * PLANE)

#define LSCALE 2048.0f              // 2^11 lo-limb scaling (kills subnormals)
#define LINV   (1.0f / 2048.0f)

// GEMM tiling: CTA 128(M) x 128(N), K-chunk 64, 512 threads (16 warps 4x4).
#define KC 64
#define NCH 16                      // 1024 / 64 chunks
#define ROWH 72                     // 64 data halfs + 8 pad
#define TILE_H (128 * ROWH)         // 9216 halfs per limb tile
#define STAGE_H (4 * TILE_H)        // Ah, Al, Wh, Wl
#define STAGE_B (STAGE_H * 2)       // 73728 bytes
#define NSTG 3
#define SMEM_BYTES (NSTG * STAGE_B) // 221184 bytes

// ---------------------------------------------------------------------------
// Device scratch
// ---------------------------------------------------------------------------
__device__ float  g_lin[(size_t)M_ROWS * D2];     // 133 MB
__device__ __half g_A[2][(size_t)M_ROWS * D1];    // 2 x 66.6 MB
__device__ __half g_W[2][(size_t)D2 * D1];        // 2 x 2 MB

// ---------------------------------------------------------------------------
// 2-limb fp16 split with scaled lo: x ~= h + l*2^-11,  l = f16((x-h)*2^11)
// ---------------------------------------------------------------------------
__global__ __launch_bounds__(256) void split2(const float* __restrict__ src,
                                              __half* __restrict__ oh,
                                              __half* __restrict__ ol, int n8) {
    int i = blockIdx.x * blockDim.x + threadIdx.x;
    if (i >= n8) return;
    const float4* s = (const float4*)(src + (size_t)i * 8);
    float4 v0 = s[0], v1 = s[1];
    float x[8] = {v0.x, v0.y, v0.z, v0.w, v1.x, v1.y, v1.z, v1.w};
    unsigned short h[8], l[8];
#pragma unroll
    for (int q = 0; q < 8; q++) {
        __half a = __float2half_rn(x[q]);
        float r = (x[q] - __half2float(a)) * LSCALE;
        h[q] = __half_as_ushort(a);
        l[q] = __half_as_ushort(__float2half_rn(r));
    }
    uint4 p;
    p.x = h[0] | ((uint32_t)h[1] << 16); p.y = h[2] | ((uint32_t)h[3] << 16);
    p.z = h[4] | ((uint32_t)h[5] << 16); p.w = h[6] | ((uint32_t)h[7] << 16);
    ((uint4*)oh)[i] = p;
    p.x = l[0] | ((uint32_t)l[1] << 16); p.y = l[2] | ((uint32_t)l[3] << 16);
    p.z = l[4] | ((uint32_t)l[5] << 16); p.w = l[6] | ((uint32_t)l[7] << 16);
    ((uint4*)ol)[i] = p;
}

// ---------------------------------------------------------------------------
// MMA / ldmatrix helpers (fp16, fp32 accumulate)
// ---------------------------------------------------------------------------
__device__ __forceinline__ void ldm4(uint32_t* r, uint32_t a) {
    asm volatile("ldmatrix.sync.aligned.m8n8.x4.shared.b16 {%0,%1,%2,%3}, [%4];"
        : "=r"(r[0]), "=r"(r[1]), "=r"(r[2]), "=r"(r[3]) : "r"(a));
}
__device__ __forceinline__ void mma_acc(float* c, const uint32_t* a, const uint32_t* b) {
    asm volatile(
        "mma.sync.aligned.m16n8k16.row.col.f32.f16.f16.f32 "
        "{%0,%1,%2,%3}, {%4,%5,%6,%7}, {%8,%9}, {%0,%1,%2,%3};"
        : "+f"(c[0]), "+f"(c[1]), "+f"(c[2]), "+f"(c[3])
        : "r"(a[0]), "r"(a[1]), "r"(a[2]), "r"(a[3]), "r"(b[0]), "r"(b[1]));
}
__device__ __forceinline__ void mma_zro(float* d, const uint32_t* a, const uint32_t* b) {
    asm volatile(
        "mma.sync.aligned.m16n8k16.row.col.f32.f16.f16.f32 "
        "{%0,%1,%2,%3}, {%4,%5,%6,%7}, {%8,%9}, {%10,%10,%10,%10};"
        : "=f"(d[0]), "=f"(d[1]), "=f"(d[2]), "=f"(d[3])
        : "r"(a[0]), "r"(a[1]), "r"(a[2]), "r"(a[3]), "r"(b[0]), "r"(b[1]),
          "f"(0.0f));
}

// ---------------------------------------------------------------------------
// GEMM: lin = A @ W^T via 3 fp16 limb products.
// hh: chain length 1 (fresh d) + RN FADD into ct -> no tensor RZ bias.
// cross (h*l' + l'*h): chained in al at 2^11 scale; final ct += al * 2^-11.
// ll dropped (<= 2^-24 relative). CTA 128x128, 512 thr, 3-stage cp.async.
// ---------------------------------------------------------------------------
__global__ __launch_bounds__(512, 1) void gemm_limb_kernel() {
    extern __shared__ __half smp[];
    const int tid = threadIdx.x, lane = tid & 31, wid = tid >> 5;
    const int wm = wid & 3, wn = wid >> 2;       // 4(M) x 4(N) warp grid
    const int r4 = lane >> 2, cq = lane & 3;
    const int nb = blockIdx.x, mb = blockIdx.y;
    const int m0 = mb * 128, n0 = nb * 128;
    uint32_t smem_base = (uint32_t)__cvta_generic_to_shared(smp);

    float ct[2][4][4], al[2][4][4];
#pragma unroll
    for (int im = 0; im < 2; im++)
#pragma unroll
        for (int jn = 0; jn < 4; jn++)
#pragma unroll
            for (int q = 0; q < 4; q++) { ct[im][jn][q] = 0.f; al[im][jn][q] = 0.f; }

    const __half* Ab = &g_A[0][0] + (size_t)m0 * D1;
    const __half* Wb = &g_W[0][0] + (size_t)n0 * D1;
    const size_t APL = (size_t)M_ROWS * D1;
    const size_t WPL = (size_t)D2 * D1;

    // fill one stage: 4 tiles x 128 rows x 8 x 16B = 4096 chunks / 512 thr = 8
    auto fill = [&](int buf, int kc) {
        int k0 = kc * KC;
        uint32_t sb = smem_base + (uint32_t)buf * STAGE_B;
#pragma unroll
        for (int i = 0; i < 8; i++) {
            int ch = i * 512 + tid;
            int tile = ch >> 10;                 // 0=Ah 1=Al 2=Wh 3=Wl
            int r = (ch >> 3) & 127;
            int q = ch & 7;
            const void* src = (tile < 2)
                ? (const void*)(Ab + (size_t)tile * APL + (size_t)r * D1 + k0 + q * 8)
                : (const void*)(Wb + (size_t)(tile - 2) * WPL + (size_t)r * D1 + k0 + q * 8);
            uint32_t dst = sb + (uint32_t)(tile * TILE_H + r * ROWH + q * 8) * 2;
            asm volatile("cp.async.cg.shared.global [%0], [%1], 16;" :: "r"(dst), "l"(src));
        }
        asm volatile("cp.async.commit_group;");
    };

    fill(0, 0);
    fill(1, 1);

    // ldmatrix per-lane address components (halfs) — verified mapping
    const int aRow = wm * 32 + (lane & 15);
    const int aK   = (lane >> 4) * 8;
    const int bRow = wn * 32 + (lane >> 4) * 8 + (lane & 7);
    const int bK   = ((lane >> 3) & 1) * 8;

    for (int s = 0; s < NCH; s++) {
        if (s + 2 < NCH) fill((s + 2) % NSTG, s + 2);       // 2 stages ahead
        if (s + 2 < NCH)      asm volatile("cp.async.wait_group 2;");
        else if (s + 1 < NCH) asm volatile("cp.async.wait_group 1;");
        else                  asm volatile("cp.async.wait_group 0;");
        __syncthreads();

        uint32_t sb = smem_base + (uint32_t)(s % NSTG) * STAGE_B;
#pragma unroll
        for (int ksub = 0; ksub < 4; ksub++) {
            uint32_t b[2][4][2];
#pragma unroll
            for (int lb = 0; lb < 2; lb++)
#pragma unroll
                for (int jp = 0; jp < 2; jp++) {
                    uint32_t bd = sb + (uint32_t)((2 + lb) * TILE_H
                                   + (bRow + jp * 16) * ROWH + ksub * 16 + bK) * 2;
                    uint32_t t[4];
                    ldm4(t, bd);
                    b[lb][jp * 2][0] = t[0];     b[lb][jp * 2][1] = t[1];
                    b[lb][jp * 2 + 1][0] = t[2]; b[lb][jp * 2 + 1][1] = t[3];
                }
            uint32_t a[2][2][4];
#pragma unroll
            for (int la = 0; la < 2; la++)
#pragma unroll
                for (int im = 0; im < 2; im++) {
                    uint32_t ad = sb + (uint32_t)(la * TILE_H + (aRow + im * 16) * ROWH
                                   + ksub * 16 + aK) * 2;
                    ldm4(a[la][im], ad);
                }
#pragma unroll
            for (int im = 0; im < 2; im++)
#pragma unroll
                for (int jn = 0; jn < 4; jn++) {
                    float t4[4];
                    mma_zro(t4, a[0][im], b[0][jn]);        // hh, fresh chain
#pragma unroll
                    for (int q = 0; q < 4; q++) ct[im][jn][q] += t4[q];
                    mma_acc(al[im][jn], a[0][im], b[1][jn]); // h * l'
                    mma_acc(al[im][jn], a[1][im], b[0][jn]); // l' * h
                }
        }
        __syncthreads();
    }

    // fold scaled cross-term accumulator, store
#pragma unroll
    for (int im = 0; im < 2; im++) {
#pragma unroll
        for (int jn = 0; jn < 4; jn++) {
#pragma unroll
            for (int q = 0; q < 4; q++)
                ct[im][jn][q] = fmaf(al[im][jn][q], LINV, ct[im][jn][q]);
            int row = m0 + wm * 32 + im * 16 + r4;
            int col = n0 + wn * 32 + jn * 8 + cq * 2;
            *(float2*)&g_lin[(size_t)row * D2 + col] =
                make_float2(ct[im][jn][0], ct[im][jn][1]);
            *(float2*)&g_lin[(size_t)(row + 8) * D2 + col] =
                make_float2(ct[im][jn][2], ct[im][jn][3]);
        }
    }
}

// ---------------------------------------------------------------------------
// LIF scan: one thread per float; streaming loads/stores (.cs).
// ---------------------------------------------------------------------------
__global__ __launch_bounds__(256, 8) void scan_kernel(float* __restrict__ out) {
    const float ALPHA = 0.7788007830714049f;  // exp(-1/4)
    const float BETA  = 0.9512294245007140f;  // exp(-1/20)

    int j = blockIdx.x * blockDim.x + threadIdx.x;  // 0..PLANE-1

    const float* lin = g_lin;
    float* spk = out;
    float* V   = spk + TOTAL;
    float* I   = V + TOTAL;

    float sx = 0.f, mx = 0.f;

    __stcs(&spk[j], 0.f); __stcs(&V[j], 0.f); __stcs(&I[j], 0.f);   // t = 0

    float cur = __ldcs(&lin[j]);

#pragma unroll 1
    for (int t = 1; t < STEPS; t++) {
        float nxt = cur;
        if (t < STEPS - 1) nxt = __ldcs(&lin[(size_t)t * PLANE + j]);

        float kx = (mx > 1.0f) ? 0.0f : 1.0f;
        sx = ALPHA * sx + cur;
        mx = (BETA * mx + sx) * kx;
        float o = (mx > 1.0f) ? 1.0f : 0.0f;

        size_t off = (size_t)t * PLANE + j;
        __stcs(&spk[off], o);
        __stcs(&V[off], mx);
        __stcs(&I[off], sx);

        cur = nxt;
    }
}

// ---------------------------------------------------------------------------
extern "C" void kernel_launch(void* const* d_in, const int* in_sizes, int n_in,
                              void* d_out, int out_size) {
    const float* input  = (const float*)d_in[0];   // [128, 256, 1024]
    const float* weight = (const float*)d_in[1];   // [1024, 1024]
    float* out = (float*)d_out;                    // [3, 128, 256, 1024]

    __half *pA, *pW;
    cudaGetSymbolAddress((void**)&pA, g_A);
    cudaGetSymbolAddress((void**)&pW, g_W);
    const size_t APL = (size_t)M_ROWS * D1;
    const size_t WPL = (size_t)D2 * D1;

    int nA8 = (M_ROWS * D1) / 8;
    int nW8 = (D2 * D1) / 8;
    split2<<<(nA8 + 255) / 256, 256>>>(input, pA, pA + APL, nA8);
    split2<<<(nW8 + 255) / 256, 256>>>(weight, pW, pW + WPL, nW8);

    cudaFuncSetAttribute(gemm_limb_kernel, cudaFuncAttributeMaxDynamicSharedMemorySize, SMEM_BYTES);
    gemm_limb_kernel<<<dim3(D2 / 128, M_ROWS / 128), 512, SMEM_BYTES>>>();

    scan_kernel<<<PLANE / 256, 256>>>(out);
}

// round 8
// speedup vs baseline: 2.3157x; 1.1028x over previous
#include <cuda_runtime.h>
#include <cuda_fp16.h>
#include <cstdint>

// ---------------------------------------------------------------------------
// Problem constants
// ---------------------------------------------------------------------------
#define STEPS 128
#define BATCH 256
#define D1 1024
#define D2 1024
#define M_ROWS (127 * BATCH)        // 32512
#define PLANE (BATCH * D2)          // 262144
#define PLANE2 (PLANE / 2)
#define TOTAL2 (STEPS * PLANE2)

#define LSCALE 2048.0f              // 2^11 lo-limb scaling (kills subnormals)
#define LINV   (1.0f / 2048.0f)

// GEMM tiling: CTA 128(M) x 128(N), K-chunk 64, 512 threads (16 warps 4x4).
#define KC 64
#define NCH 16                      // 1024 / 64 chunks
#define ROWH 72                     // 64 data halfs + 8 pad
#define TILE_H (128 * ROWH)         // 9216 halfs per limb tile
#define STAGE_H (4 * TILE_H)        // Ah, Al, Wh, Wl
#define STAGE_B (STAGE_H * 2)       // 73728 bytes
#define NSTG 3
#define SMEM_BYTES (NSTG * STAGE_B) // 221184 bytes

// ---------------------------------------------------------------------------
// Device scratch
// ---------------------------------------------------------------------------
__device__ float  g_lin[(size_t)M_ROWS * D2];     // 133 MB
__device__ __half g_A[2][(size_t)M_ROWS * D1];    // 2 x 66.6 MB
__device__ __half g_W[2][(size_t)D2 * D1];        // 2 x 2 MB

// ---------------------------------------------------------------------------
// 2-limb fp16 split with scaled lo: x ~= h + l*2^-11,  l = f16((x-h)*2^11)
// ---------------------------------------------------------------------------
__global__ __launch_bounds__(256) void split2(const float* __restrict__ src,
                                              __half* __restrict__ oh,
                                              __half* __restrict__ ol, int n8) {
    int i = blockIdx.x * blockDim.x + threadIdx.x;
    if (i >= n8) return;
    const float4* s = (const float4*)(src + (size_t)i * 8);
    float4 v0 = s[0], v1 = s[1];
    float x[8] = {v0.x, v0.y, v0.z, v0.w, v1.x, v1.y, v1.z, v1.w};
    unsigned short h[8], l[8];
#pragma unroll
    for (int q = 0; q < 8; q++) {
        __half a = __float2half_rn(x[q]);
        float r = (x[q] - __half2float(a)) * LSCALE;
        h[q] = __half_as_ushort(a);
        l[q] = __half_as_ushort(__float2half_rn(r));
    }
    uint4 p;
    p.x = h[0] | ((uint32_t)h[1] << 16); p.y = h[2] | ((uint32_t)h[3] << 16);
    p.z = h[4] | ((uint32_t)h[5] << 16); p.w = h[6] | ((uint32_t)h[7] << 16);
    ((uint4*)oh)[i] = p;
    p.x = l[0] | ((uint32_t)l[1] << 16); p.y = l[2] | ((uint32_t)l[3] << 16);
    p.z = l[4] | ((uint32_t)l[5] << 16); p.w = l[6] | ((uint32_t)l[7] << 16);
    ((uint4*)ol)[i] = p;
}

// ---------------------------------------------------------------------------
// MMA / ldmatrix helpers (fp16, fp32 accumulate)
// ---------------------------------------------------------------------------
__device__ __forceinline__ void ldm4(uint32_t* r, uint32_t a) {
    asm volatile("ldmatrix.sync.aligned.m8n8.x4.shared.b16 {%0,%1,%2,%3}, [%4];"
        : "=r"(r[0]), "=r"(r[1]), "=r"(r[2]), "=r"(r[3]) : "r"(a));
}
__device__ __forceinline__ void mma_acc(float* c, const uint32_t* a, const uint32_t* b) {
    asm volatile(
        "mma.sync.aligned.m16n8k16.row.col.f32.f16.f16.f32 "
        "{%0,%1,%2,%3}, {%4,%5,%6,%7}, {%8,%9}, {%0,%1,%2,%3};"
        : "+f"(c[0]), "+f"(c[1]), "+f"(c[2]), "+f"(c[3])
        : "r"(a[0]), "r"(a[1]), "r"(a[2]), "r"(a[3]), "r"(b[0]), "r"(b[1]));
}
__device__ __forceinline__ void mma_zro(float* d, const uint32_t* a, const uint32_t* b) {
    asm volatile(
        "mma.sync.aligned.m16n8k16.row.col.f32.f16.f16.f32 "
        "{%0,%1,%2,%3}, {%4,%5,%6,%7}, {%8,%9}, {%10,%10,%10,%10};"
        : "=f"(d[0]), "=f"(d[1]), "=f"(d[2]), "=f"(d[3])
        : "r"(a[0]), "r"(a[1]), "r"(a[2]), "r"(a[3]), "r"(b[0]), "r"(b[1]),
          "f"(0.0f));
}

// ---------------------------------------------------------------------------
// GEMM: lin = A @ W^T via 3 fp16 limb products.
// hh: chain length 2 (one k32 pair per fresh chain) then RN FADD into ct --
// empirically-validated anti-RZ scheme (round 5/6). Cross (h*l' + l'*h):
// chained in al at 2^11 scale; final ct += al * 2^-11. ll dropped.
// CTA 128x128, 512 thr, 3-stage cp.async pipeline, ONE sync per chunk.
// ---------------------------------------------------------------------------
__global__ __launch_bounds__(512, 1) void gemm_limb_kernel() {
    extern __shared__ __half smp[];
    const int tid = threadIdx.x, lane = tid & 31, wid = tid >> 5;
    const int wm = wid & 3, wn = wid >> 2;       // 4(M) x 4(N) warp grid
    const int r4 = lane >> 2, cq = lane & 3;
    const int nb = blockIdx.x, mb = blockIdx.y;
    const int m0 = mb * 128, n0 = nb * 128;
    uint32_t smem_base = (uint32_t)__cvta_generic_to_shared(smp);

    float ct[2][4][4], al[2][4][4];
#pragma unroll
    for (int im = 0; im < 2; im++)
#pragma unroll
        for (int jn = 0; jn < 4; jn++)
#pragma unroll
            for (int q = 0; q < 4; q++) { ct[im][jn][q] = 0.f; al[im][jn][q] = 0.f; }

    const __half* Ab = &g_A[0][0] + (size_t)m0 * D1;
    const __half* Wb = &g_W[0][0] + (size_t)n0 * D1;
    const size_t APL = (size_t)M_ROWS * D1;
    const size_t WPL = (size_t)D2 * D1;

    // fill one stage: 4 tiles x 128 rows x 8 x 16B = 4096 chunks / 512 thr = 8
    auto fill = [&](int buf, int kc) {
        int k0 = kc * KC;
        uint32_t sb = smem_base + (uint32_t)buf * STAGE_B;
#pragma unroll
        for (int i = 0; i < 8; i++) {
            int ch = i * 512 + tid;
            int tile = ch >> 10;                 // 0=Ah 1=Al 2=Wh 3=Wl
            int r = (ch >> 3) & 127;
            int q = ch & 7;
            const void* src = (tile < 2)
                ? (const void*)(Ab + (size_t)tile * APL + (size_t)r * D1 + k0 + q * 8)
                : (const void*)(Wb + (size_t)(tile - 2) * WPL + (size_t)r * D1 + k0 + q * 8);
            uint32_t dst = sb + (uint32_t)(tile * TILE_H + r * ROWH + q * 8) * 2;
            asm volatile("cp.async.cg.shared.global [%0], [%1], 16;" :: "r"(dst), "l"(src));
        }
        asm volatile("cp.async.commit_group;");
    };

    fill(0, 0);
    fill(1, 1);

    // ldmatrix per-lane address components (halfs) — verified mapping
    const int aRow = wm * 32 + (lane & 15);
    const int aK   = (lane >> 4) * 8;
    const int bRow = wn * 32 + (lane >> 4) * 8 + (lane & 7);
    const int bK   = ((lane >> 3) & 1) * 8;

    for (int s = 0; s < NCH; s++) {
        if (s < NCH - 1) asm volatile("cp.async.wait_group 1;");
        else             asm volatile("cp.async.wait_group 0;");
        __syncthreads();                          // single barrier per chunk

        uint32_t sb = smem_base + (uint32_t)(s % NSTG) * STAGE_B;
#pragma unroll
        for (int kp = 0; kp < 2; kp++) {          // pairs of k16 steps
            // limb-0 fragments for BOTH k16 halves of the pair
            uint32_t a0[2][2][4];                 // [ks][im]
            uint32_t b0[2][4][2];                 // [ks][jn]
#pragma unroll
            for (int ks = 0; ks < 2; ks++) {
                int ksub = kp * 2 + ks;
#pragma unroll
                for (int im = 0; im < 2; im++) {
                    uint32_t ad = sb + (uint32_t)((aRow + im * 16) * ROWH
                                   + ksub * 16 + aK) * 2;
                    ldm4(a0[ks][im], ad);
                }
#pragma unroll
                for (int jp = 0; jp < 2; jp++) {
                    uint32_t bd = sb + (uint32_t)(2 * TILE_H
                                   + (bRow + jp * 16) * ROWH + ksub * 16 + bK) * 2;
                    uint32_t t[4];
                    ldm4(t, bd);
                    b0[ks][jp * 2][0] = t[0];     b0[ks][jp * 2][1] = t[1];
                    b0[ks][jp * 2 + 1][0] = t[2]; b0[ks][jp * 2 + 1][1] = t[3];
                }
            }
            // hh: fresh chain over the k32 pair, then RN dump
#pragma unroll
            for (int im = 0; im < 2; im++)
#pragma unroll
                for (int jn = 0; jn < 4; jn++) {
                    float t4[4];
                    mma_zro(t4, a0[0][im], b0[0][jn]);
                    mma_acc(t4, a0[1][im], b0[1][jn]);
#pragma unroll
                    for (int q = 0; q < 4; q++) ct[im][jn][q] += t4[q];
                }
            // cross terms per k16 (lo-limb frags transient)
#pragma unroll
            for (int ks = 0; ks < 2; ks++) {
                int ksub = kp * 2 + ks;
                uint32_t a1[2][4], b1[4][2];
#pragma unroll
                for (int im = 0; im < 2; im++) {
                    uint32_t ad = sb + (uint32_t)(TILE_H + (aRow + im * 16) * ROWH
                                   + ksub * 16 + aK) * 2;
                    ldm4(a1[im], ad);
                }
#pragma unroll
                for (int jp = 0; jp < 2; jp++) {
                    uint32_t bd = sb + (uint32_t)(3 * TILE_H
                                   + (bRow + jp * 16) * ROWH + ksub * 16 + bK) * 2;
                    uint32_t t[4];
                    ldm4(t, bd);
                    b1[jp * 2][0] = t[0];     b1[jp * 2][1] = t[1];
                    b1[jp * 2 + 1][0] = t[2]; b1[jp * 2 + 1][1] = t[3];
                }
#pragma unroll
                for (int im = 0; im < 2; im++)
#pragma unroll
                    for (int jn = 0; jn < 4; jn++) {
                        mma_acc(al[im][jn], a0[ks][im], b1[jn]);  // h * l'
                        mma_acc(al[im][jn], a1[im], b0[ks][jn]);  // l' * h
                    }
            }
        }
        if (s + 2 < NCH) fill((s + 2) % NSTG, s + 2);   // after compute: safe
    }

    // fold scaled cross-term accumulator, store
#pragma unroll
    for (int im = 0; im < 2; im++) {
#pragma unroll
        for (int jn = 0; jn < 4; jn++) {
#pragma unroll
            for (int q = 0; q < 4; q++)
                ct[im][jn][q] = fmaf(al[im][jn][q], LINV, ct[im][jn][q]);
            int row = m0 + wm * 32 + im * 16 + r4;
            int col = n0 + wn * 32 + jn * 8 + cq * 2;
            *(float2*)&g_lin[(size_t)row * D2 + col] =
                make_float2(ct[im][jn][0], ct[im][jn][1]);
            *(float2*)&g_lin[(size_t)(row + 8) * D2 + col] =
                make_float2(ct[im][jn][2], ct[im][jn][3]);
        }
    }
}

// ---------------------------------------------------------------------------
// LIF scan: one thread per float2 (best-measured variant, 101.6 us).
// ---------------------------------------------------------------------------
__global__ __launch_bounds__(256, 8) void scan_kernel(float* __restrict__ out) {
    const float ALPHA = 0.7788007830714049f;  // exp(-1/4)
    const float BETA  = 0.9512294245007140f;  // exp(-1/20)

    int j = blockIdx.x * blockDim.x + threadIdx.x;

    const float2* lin = (const float2*)g_lin;
    float2* spk = (float2*)out;
    float2* V   = spk + TOTAL2;
    float2* I   = V + TOTAL2;

    float sx = 0.f, sy = 0.f, mx = 0.f, my = 0.f;

    float2 z = make_float2(0.f, 0.f);
    spk[j] = z; V[j] = z; I[j] = z;

    float2 cur = lin[j];

#pragma unroll 1
    for (int t = 1; t < STEPS; t++) {
        float2 nxt = cur;
        if (t < STEPS - 1) nxt = lin[(size_t)t * PLANE2 + j];

        float kx = (mx > 1.0f) ? 0.0f : 1.0f;
        float ky = (my > 1.0f) ? 0.0f : 1.0f;

        sx = ALPHA * sx + cur.x;
        sy = ALPHA * sy + cur.y;
        mx = (BETA * mx + sx) * kx;
        my = (BETA * my + sy) * ky;

        float2 o;
        o.x = (mx > 1.0f) ? 1.0f : 0.0f;
        o.y = (my > 1.0f) ? 1.0f : 0.0f;

        size_t off = (size_t)t * PLANE2 + j;
        spk[off] = o;
        V[off]   = make_float2(mx, my);
        I[off]   = make_float2(sx, sy);

        cur = nxt;
    }
}

// ---------------------------------------------------------------------------
extern "C" void kernel_launch(void* const* d_in, const int* in_sizes, int n_in,
                              void* d_out, int out_size) {
    const float* input  = (const float*)d_in[0];   // [128, 256, 1024]
    const float* weight = (const float*)d_in[1];   // [1024, 1024]
    float* out = (float*)d_out;                    // [3, 128, 256, 1024]

    __half *pA, *pW;
    cudaGetSymbolAddress((void**)&pA, g_A);
    cudaGetSymbolAddress((void**)&pW, g_W);
    const size_t APL = (size_t)M_ROWS * D1;
    const size_t WPL = (size_t)D2 * D1;

    int nA8 = (M_ROWS * D1) / 8;
    int nW8 = (D2 * D1) / 8;
    split2<<<(nA8 + 255) / 256, 256>>>(input, pA, pA + APL, nA8);
    split2<<<(nW8 + 255) / 256, 256>>>(weight, pW, pW + WPL, nW8);

    cudaFuncSetAttribute(gemm_limb_kernel, cudaFuncAttributeMaxDynamicSharedMemorySize, SMEM_BYTES);
    gemm_limb_kernel<<<dim3(D2 / 128, M_ROWS / 128), 512, SMEM_BYTES>>>();

    scan_kernel<<<PLANE2 / 256, 256>>>(out);
}

// round 10
// speedup vs baseline: 2.3469x; 1.0135x over previous
#include <cuda_runtime.h>
#include <cuda_fp16.h>
#include <cstdint>

// ---------------------------------------------------------------------------
// Problem constants
// ---------------------------------------------------------------------------
#define STEPS 128
#define BATCH 256
#define D1 1024
#define D2 1024
#define M_ROWS (127 * BATCH)        // 32512
#define PLANE (BATCH * D2)          // 262144
#define PLANE2 (PLANE / 2)
#define TOTAL2 (STEPS * PLANE2)

#define LSCALE 2048.0f              // 2^11 lo-limb scaling (kills subnormals)
#define LINV   (1.0f / 2048.0f)

// GEMM tiling: CTA 128(M) x 64(N), K-chunk 64, 256 threads (8 warps 4x2),
// 2-stage pipeline, 2 CTAs per SM.
#define KC 64
#define NCH 16                      // 1024 / 64 chunks
#define ROWH 72                     // 64 data halfs + 8 pad
#define TA_H (128 * ROWH)           // 9216 halfs per A limb tile
#define TB_H (64 * ROWH)            // 4608 halfs per W limb tile
#define WOFF_H (2 * TA_H)           // W tiles after the 2 A tiles
#define STAGE_H (2 * TA_H + 2 * TB_H)  // 27648 halfs
#define STAGE_B (STAGE_H * 2)       // 55296 bytes
#define SMEM_BYTES (2 * STAGE_B)    // 110592 bytes -> 2 CTAs/SM

// ---------------------------------------------------------------------------
// Device scratch
// ---------------------------------------------------------------------------
__device__ float  g_lin[(size_t)M_ROWS * D2];     // 133 MB
__device__ __half g_A[2][(size_t)M_ROWS * D1];    // 2 x 66.6 MB
__device__ __half g_W[2][(size_t)D2 * D1];        // 2 x 2 MB

// ---------------------------------------------------------------------------
// 2-limb fp16 split with scaled lo: x ~= h + l*2^-11,  l = f16((x-h)*2^11)
// ---------------------------------------------------------------------------
__global__ __launch_bounds__(256) void split2(const float* __restrict__ src,
                                              __half* __restrict__ oh,
                                              __half* __restrict__ ol, int n8) {
    int i = blockIdx.x * blockDim.x + threadIdx.x;
    if (i >= n8) return;
    const float4* s = (const float4*)(src + (size_t)i * 8);
    float4 v0 = s[0], v1 = s[1];
    float x[8] = {v0.x, v0.y, v0.z, v0.w, v1.x, v1.y, v1.z, v1.w};
    unsigned short h[8], l[8];
#pragma unroll
    for (int q = 0; q < 8; q++) {
        __half a = __float2half_rn(x[q]);
        float r = (x[q] - __half2float(a)) * LSCALE;
        h[q] = __half_as_ushort(a);
        l[q] = __half_as_ushort(__float2half_rn(r));
    }
    uint4 p;
    p.x = h[0] | ((uint32_t)h[1] << 16); p.y = h[2] | ((uint32_t)h[3] << 16);
    p.z = h[4] | ((uint32_t)h[5] << 16); p.w = h[6] | ((uint32_t)h[7] << 16);
    ((uint4*)oh)[i] = p;
    p.x = l[0] | ((uint32_t)l[1] << 16); p.y = l[2] | ((uint32_t)l[3] << 16);
    p.z = l[4] | ((uint32_t)l[5] << 16); p.w = l[6] | ((uint32_t)l[7] << 16);
    ((uint4*)ol)[i] = p;
}

// ---------------------------------------------------------------------------
// MMA / ldmatrix helpers (fp16, fp32 accumulate)
// ---------------------------------------------------------------------------
__device__ __forceinline__ void ldm4(uint32_t* r, uint32_t a) {
    asm volatile("ldmatrix.sync.aligned.m8n8.x4.shared.b16 {%0,%1,%2,%3}, [%4];"
        : "=r"(r[0]), "=r"(r[1]), "=r"(r[2]), "=r"(r[3]) : "r"(a));
}
__device__ __forceinline__ void mma_acc(float* c, const uint32_t* a, const uint32_t* b) {
    asm volatile(
        "mma.sync.aligned.m16n8k16.row.col.f32.f16.f16.f32 "
        "{%0,%1,%2,%3}, {%4,%5,%6,%7}, {%8,%9}, {%0,%1,%2,%3};"
        : "+f"(c[0]), "+f"(c[1]), "+f"(c[2]), "+f"(c[3])
        : "r"(a[0]), "r"(a[1]), "r"(a[2]), "r"(a[3]), "r"(b[0]), "r"(b[1]));
}
__device__ __forceinline__ void mma_zro(float* d, const uint32_t* a, const uint32_t* b) {
    asm volatile(
        "mma.sync.aligned.m16n8k16.row.col.f32.f16.f16.f32 "
        "{%0,%1,%2,%3}, {%4,%5,%6,%7}, {%8,%9}, {%10,%10,%10,%10};"
        : "=f"(d[0]), "=f"(d[1]), "=f"(d[2]), "=f"(d[3])
        : "r"(a[0]), "r"(a[1]), "r"(a[2]), "r"(a[3]), "r"(b[0]), "r"(b[1]),
          "f"(0.0f));
}

// ---------------------------------------------------------------------------
// GEMM: lin = A @ W^T via 3 fp16 limb products (numerics identical to round 8:
// hh chain-2 per k32 pair + RN FADD into ct; cross terms chained in al at 2^11
// scale; ct += al * 2^-11 at the end).
// CTA 128x64, 256 thr, 2-stage cp.async pipeline (correct 2-barrier schedule),
// 2 CTAs/SM so one CTA's HMMAs cover the other's barrier drains.
// ---------------------------------------------------------------------------
__global__ __launch_bounds__(256, 2) void gemm_limb_kernel() {
    extern __shared__ __half smp[];
    const int tid = threadIdx.x, lane = tid & 31, wid = tid >> 5;
    const int wm = wid & 3, wn = wid >> 2;       // 4(M) x 2(N) warp grid
    const int r4 = lane >> 2, cq = lane & 3;
    const int nb = blockIdx.x, mb = blockIdx.y;
    const int m0 = mb * 128, n0 = nb * 64;
    uint32_t smem_base = (uint32_t)__cvta_generic_to_shared(smp);

    float ct[2][4][4], al[2][4][4];
#pragma unroll
    for (int im = 0; im < 2; im++)
#pragma unroll
        for (int jn = 0; jn < 4; jn++)
#pragma unroll
            for (int q = 0; q < 4; q++) { ct[im][jn][q] = 0.f; al[im][jn][q] = 0.f; }

    const __half* Ab = &g_A[0][0] + (size_t)m0 * D1;
    const __half* Wb = &g_W[0][0] + (size_t)n0 * D1;
    const size_t APL = (size_t)M_ROWS * D1;
    const size_t WPL = (size_t)D2 * D1;

    // fill one stage: A 2x128 rows + W 2x64 rows, 8x16B per row -> 3072 chunks
    auto fill = [&](int buf, int kc) {
        int k0 = kc * KC;
        uint32_t sb = smem_base + (uint32_t)buf * STAGE_B;
#pragma unroll
        for (int i = 0; i < 8; i++) {            // A: 2048 chunks
            int ch = i * 256 + tid;
            int tile = ch >> 10;                 // 0=Ah 1=Al
            int r = (ch >> 3) & 127;
            int q = ch & 7;
            const void* src = Ab + (size_t)tile * APL + (size_t)r * D1 + k0 + q * 8;
            uint32_t dst = sb + (uint32_t)(tile * TA_H + r * ROWH + q * 8) * 2;
            asm volatile("cp.async.cg.shared.global [%0], [%1], 16;" :: "r"(dst), "l"(src));
        }
#pragma unroll
        for (int i = 0; i < 4; i++) {            // W: 1024 chunks
            int ch = i * 256 + tid;
            int tile = ch >> 9;                  // 0=Wh 1=Wl
            int r = (ch >> 3) & 63;
            int q = ch & 7;
            const void* src = Wb + (size_t)tile * WPL + (size_t)r * D1 + k0 + q * 8;
            uint32_t dst = sb + (uint32_t)(WOFF_H + tile * TB_H + r * ROWH + q * 8) * 2;
            asm volatile("cp.async.cg.shared.global [%0], [%1], 16;" :: "r"(dst), "l"(src));
        }
        asm volatile("cp.async.commit_group;");
    };

    fill(0, 0);
    fill(1, 1);

    // ldmatrix per-lane address components (halfs) — verified mapping
    const int aRow = wm * 32 + (lane & 15);
    const int aK   = (lane >> 4) * 8;
    const int bRow = wn * 32 + (lane >> 4) * 8 + (lane & 7);
    const int bK   = ((lane >> 3) & 1) * 8;

    for (int s = 0; s < NCH; s++) {
        // fill(s) must be complete: pending groups are fill(s), fill(s+1)
        if (s < NCH - 1) asm volatile("cp.async.wait_group 1;");
        else             asm volatile("cp.async.wait_group 0;");
        __syncthreads();                          // make fill(s) visible to all

        uint32_t sb = smem_base + (uint32_t)(s & 1) * STAGE_B;
#pragma unroll
        for (int kp = 0; kp < 2; kp++) {          // pairs of k16 steps
            uint32_t a0[2][2][4];                 // [ks][im]
            uint32_t b0[2][4][2];                 // [ks][jn]
#pragma unroll
            for (int ks = 0; ks < 2; ks++) {
                int ksub = kp * 2 + ks;
#pragma unroll
                for (int im = 0; im < 2; im++) {
                    uint32_t ad = sb + (uint32_t)((aRow + im * 16) * ROWH
                                   + ksub * 16 + aK) * 2;
                    ldm4(a0[ks][im], ad);
                }
                {
                    uint32_t bd = sb + (uint32_t)(WOFF_H
                                   + bRow * ROWH + ksub * 16 + bK) * 2;
                    uint32_t t[4];
                    ldm4(t, bd);
                    b0[ks][0][0] = t[0]; b0[ks][0][1] = t[1];
                    b0[ks][1][0] = t[2]; b0[ks][1][1] = t[3];
                    bd = sb + (uint32_t)(WOFF_H
                         + (bRow + 16) * ROWH + ksub * 16 + bK) * 2;
                    ldm4(t, bd);
                    b0[ks][2][0] = t[0]; b0[ks][2][1] = t[1];
                    b0[ks][3][0] = t[2]; b0[ks][3][1] = t[3];
                }
            }
            // hh: fresh chain over the k32 pair, then RN dump
#pragma unroll
            for (int im = 0; im < 2; im++)
#pragma unroll
                for (int jn = 0; jn < 4; jn++) {
                    float t4[4];
                    mma_zro(t4, a0[0][im], b0[0][jn]);
                    mma_acc(t4, a0[1][im], b0[1][jn]);
#pragma unroll
                    for (int q = 0; q < 4; q++) ct[im][jn][q] += t4[q];
                }
            // cross terms per k16 (lo-limb frags transient)
#pragma unroll
            for (int ks = 0; ks < 2; ks++) {
                int ksub = kp * 2 + ks;
                uint32_t a1[2][4], b1[4][2];
#pragma unroll
                for (int im = 0; im < 2; im++) {
                    uint32_t ad = sb + (uint32_t)(TA_H + (aRow + im * 16) * ROWH
                                   + ksub * 16 + aK) * 2;
                    ldm4(a1[im], ad);
                }
                {
                    uint32_t bd = sb + (uint32_t)(WOFF_H + TB_H
                                   + bRow * ROWH + ksub * 16 + bK) * 2;
                    uint32_t t[4];
                    ldm4(t, bd);
                    b1[0][0] = t[0]; b1[0][1] = t[1];
                    b1[1][0] = t[2]; b1[1][1] = t[3];
                    bd = sb + (uint32_t)(WOFF_H + TB_H
                         + (bRow + 16) * ROWH + ksub * 16 + bK) * 2;
                    ldm4(t, bd);
                    b1[2][0] = t[0]; b1[2][1] = t[1];
                    b1[3][0] = t[2]; b1[3][1] = t[3];
                }
#pragma unroll
                for (int im = 0; im < 2; im++)
#pragma unroll
                    for (int jn = 0; jn < 4; jn++) {
                        mma_acc(al[im][jn], a0[ks][im], b1[jn]);  // h * l'
                        mma_acc(al[im][jn], a1[im], b0[ks][jn]);  // l' * h
                    }
            }
        }
        // all warps finished reading stage s; now its buffer may be refilled
        __syncthreads();
        if (s + 2 < NCH) fill(s & 1, s + 2);
    }

    // fold scaled cross-term accumulator, store
#pragma unroll
    for (int im = 0; im < 2; im++) {
#pragma unroll
        for (int jn = 0; jn < 4; jn++) {
#pragma unroll
            for (int q = 0; q < 4; q++)
                ct[im][jn][q] = fmaf(al[im][jn][q], LINV, ct[im][jn][q]);
            int row = m0 + wm * 32 + im * 16 + r4;
            int col = n0 + wn * 32 + jn * 8 + cq * 2;
            *(float2*)&g_lin[(size_t)row * D2 + col] =
                make_float2(ct[im][jn][0], ct[im][jn][1]);
            *(float2*)&g_lin[(size_t)(row + 8) * D2 + col] =
                make_float2(ct[im][jn][2], ct[im][jn][3]);
        }
    }
}

// ---------------------------------------------------------------------------
// LIF scan: one thread per float2 (best-measured config: 512 x 256).
// ---------------------------------------------------------------------------
__global__ __launch_bounds__(256, 8) void scan_kernel(float* __restrict__ out) {
    const float ALPHA = 0.7788007830714049f;  // exp(-1/4)
    const float BETA  = 0.9512294245007140f;  // exp(-1/20)

    int j = blockIdx.x * blockDim.x + threadIdx.x;

    const float2* lin = (const float2*)g_lin;
    float2* spk = (float2*)out;
    float2* V   = spk + TOTAL2;
    float2* I   = V + TOTAL2;

    float sx = 0.f, sy = 0.f, mx = 0.f, my = 0.f;

    float2 z = make_float2(0.f, 0.f);
    spk[j] = z; V[j] = z; I[j] = z;

    float2 cur = lin[j];

#pragma unroll 1
    for (int t = 1; t < STEPS; t++) {
        float2 nxt = cur;
        if (t < STEPS - 1) nxt = lin[(size_t)t * PLANE2 + j];

        float kx = (mx > 1.0f) ? 0.0f : 1.0f;
        float ky = (my > 1.0f) ? 0.0f : 1.0f;

        sx = ALPHA * sx + cur.x;
        sy = ALPHA * sy + cur.y;
        mx = (BETA * mx + sx) * kx;
        my = (BETA * my + sy) * ky;

        float2 o;
        o.x = (mx > 1.0f) ? 1.0f : 0.0f;
        o.y = (my > 1.0f) ? 1.0f : 0.0f;

        size_t off = (size_t)t * PLANE2 + j;
        spk[off] = o;
        V[off]   = make_float2(mx, my);
        I[off]   = make_float2(sx, sy);

        cur = nxt;
    }
}

// ---------------------------------------------------------------------------
extern "C" void kernel_launch(void* const* d_in, const int* in_sizes, int n_in,
                              void* d_out, int out_size) {
    const float* input  = (const float*)d_in[0];   // [128, 256, 1024]
    const float* weight = (const float*)d_in[1];   // [1024, 1024]
    float* out = (float*)d_out;                    // [3, 128, 256, 1024]

    __half *pA, *pW;
    cudaGetSymbolAddress((void**)&pA, g_A);
    cudaGetSymbolAddress((void**)&pW, g_W);
    const size_t APL = (size_t)M_ROWS * D1;
    const size_t WPL = (size_t)D2 * D1;

    int nA8 = (M_ROWS * D1) / 8;
    int nW8 = (D2 * D1) / 8;
    split2<<<(nA8 + 255) / 256, 256>>>(input, pA, pA + APL, nA8);
    split2<<<(nW8 + 255) / 256, 256>>>(weight, pW, pW + WPL, nW8);

    cudaFuncSetAttribute(gemm_limb_kernel, cudaFuncAttributeMaxDynamicSharedMemorySize, SMEM_BYTES);
    gemm_limb_kernel<<<dim3(D2 / 64, M_ROWS / 128), 256, SMEM_BYTES>>>();

    scan_kernel<<<PLANE2 / 256, 256>>>(out);
}